// round 1
// baseline (speedup 1.0000x reference)
#include <cuda_runtime.h>

// BilinearInteractionV2: out[b,p,e] = (sum_d emb[b,l(p),d] * W[p,d,e]) * emb[b,r(p),e]
// Shapes: emb [2048,40,64] f32, W [780,64,64] f32, l/r idx [780] i32, out [2048,780,64] f32.

constexpr int NF    = 40;
constexpr int EMB   = 64;
constexpr int BATCH = 2048;
constexpr int PAIRS = 780;
constexpr int TB    = 128;   // batch rows per block

__global__ __launch_bounds__(256)
void bilinear_v2_kernel(const float* __restrict__ emb,
                        const float* __restrict__ W,
                        const int*   __restrict__ lidx,
                        const int*   __restrict__ ridx,
                        float*       __restrict__ out)
{
    __shared__ float sW[EMB][EMB];   // sW[d][e] = W[p][d][e]   (16 KB)
    __shared__ float sL[TB][EMB];    // left-emb tile           (32 KB)

    const int p   = blockIdx.x;
    const int b0  = blockIdx.y * TB;
    const int tid = threadIdx.x;
    const int l   = lidx[p];
    const int r   = ridx[p];

    // --- stage W[p] (64x64 = 1024 float4) ---
    {
        const float4* src = reinterpret_cast<const float4*>(W + p * (EMB * EMB));
        float4*       dst = reinterpret_cast<float4*>(&sW[0][0]);
        #pragma unroll
        for (int i = 0; i < 4; i++)
            dst[tid + i * 256] = src[tid + i * 256];
    }
    // --- stage left tile (128 rows x 64 floats = 2048 float4) ---
    {
        #pragma unroll
        for (int i = 0; i < 8; i++) {
            int idx = tid + i * 256;        // 0..2047
            int row = idx >> 4;             // 0..127
            int q   = idx & 15;             // float4 slot within row
            reinterpret_cast<float4*>(&sL[row][0])[q] =
                reinterpret_cast<const float4*>(emb + ((b0 + row) * NF + l) * EMB)[q];
        }
    }
    __syncthreads();

    // --- compute: each thread owns an 8(row) x 4(col) micro-tile ---
    const int tx = tid & 15;   // 16 col-groups of 4
    const int ty = tid >> 4;   // 16 row-groups of 8

    float acc[8][4];
    #pragma unroll
    for (int i = 0; i < 8; i++)
        #pragma unroll
        for (int c = 0; c < 4; c++) acc[i][c] = 0.0f;

    #pragma unroll
    for (int k = 0; k < EMB; k += 4) {
        float4 wv[4];
        #pragma unroll
        for (int kk = 0; kk < 4; kk++)
            wv[kk] = *reinterpret_cast<const float4*>(&sW[k + kk][tx * 4]);
        #pragma unroll
        for (int i = 0; i < 8; i++) {
            float4 lv = *reinterpret_cast<const float4*>(&sL[ty * 8 + i][k]);
            const float lf[4] = {lv.x, lv.y, lv.z, lv.w};
            #pragma unroll
            for (int kk = 0; kk < 4; kk++) {
                acc[i][0] = fmaf(lf[kk], wv[kk].x, acc[i][0]);
                acc[i][1] = fmaf(lf[kk], wv[kk].y, acc[i][1]);
                acc[i][2] = fmaf(lf[kk], wv[kk].z, acc[i][2]);
                acc[i][3] = fmaf(lf[kk], wv[kk].w, acc[i][3]);
            }
        }
    }

    // --- epilogue: multiply by right-emb (L2-resident), coalesced f4 store ---
    #pragma unroll
    for (int i = 0; i < 8; i++) {
        int row = b0 + ty * 8 + i;
        float4 rv = *reinterpret_cast<const float4*>(
            emb + (row * NF + r) * EMB + tx * 4);
        float4 o;
        o.x = acc[i][0] * rv.x;
        o.y = acc[i][1] * rv.y;
        o.z = acc[i][2] * rv.z;
        o.w = acc[i][3] * rv.w;
        *reinterpret_cast<float4*>(
            out + ((size_t)row * PAIRS + p) * EMB + tx * 4) = o;
    }
}

extern "C" void kernel_launch(void* const* d_in, const int* in_sizes, int n_in,
                              void* d_out, int out_size)
{
    const float* emb  = (const float*)d_in[0];
    const float* W    = (const float*)d_in[1];
    const int*   lidx = (const int*)d_in[2];
    const int*   ridx = (const int*)d_in[3];
    float*       out  = (float*)d_out;

    dim3 grid(PAIRS, BATCH / TB);
    bilinear_v2_kernel<<<grid, 256>>>(emb, W, lidx, ridx, out);
}

// round 3
// speedup vs baseline: 1.3356x; 1.3356x over previous
#include <cuda_runtime.h>
#include <cstdint>

// out[b,p,e] = (sum_d emb[b,l(p),d] * W[p,d,e]) * emb[b,r(p),e]
// emb [2048,40,64] f32, W [780,64,64] f32, idx [780] i32, out [2048,780,64] f32

constexpr int NF    = 40;
constexpr int EMB   = 64;
constexpr int BATCH = 2048;
constexpr int PAIRS = 780;
constexpr int TB    = 256;                 // batch rows per block
constexpr int LPAD  = 68;                  // smem row stride (== 4 mod 32 -> conflict-free frags)
constexpr int SMEM_BYTES = (TB * LPAD + EMB * LPAD) * 4;   // 87,040 B

__device__ __forceinline__ uint32_t f2tf32(float x) {
    uint32_t r;
    asm("cvt.rna.tf32.f32 %0, %1;" : "=r"(r) : "f"(x));
    return r;
}

__device__ __forceinline__ void mma_tf32(float c[4],
                                         uint32_t a0, uint32_t a1, uint32_t a2, uint32_t a3,
                                         uint32_t b0, uint32_t b1) {
    asm volatile(
        "mma.sync.aligned.m16n8k8.row.col.f32.tf32.tf32.f32 "
        "{%0,%1,%2,%3}, {%4,%5,%6,%7}, {%8,%9}, {%0,%1,%2,%3};"
        : "+f"(c[0]), "+f"(c[1]), "+f"(c[2]), "+f"(c[3])
        : "r"(a0), "r"(a1), "r"(a2), "r"(a3), "r"(b0), "r"(b1));
}

extern __shared__ uint32_t smem[];   // sL [TB][LPAD] then sWt [EMB][LPAD] (tf32 bits)

__global__ __launch_bounds__(256)
void bilinear_mma_kernel(const float* __restrict__ emb,
                         const float* __restrict__ W,
                         const int*   __restrict__ lidx,
                         const int*   __restrict__ ridx,
                         float*       __restrict__ out)
{
    uint32_t* sL  = smem;                 // left tile, tf32 bits, [row][k] stride LPAD
    uint32_t* sWt = smem + TB * LPAD;     // W transposed: sWt[e][d], stride LPAD

    const int p   = blockIdx.x;
    const int b0  = blockIdx.y * TB;
    const int tid = threadIdx.x;
    const int l   = lidx[p];
    const int r   = ridx[p];

    // ---- stage left tile: 256 rows x 64 k, convert to tf32 ----
    // 4096 float4; thread handles 16. idx -> (row = idx>>4, q = idx&15)
    #pragma unroll
    for (int i = 0; i < 16; i++) {
        int idx = tid + i * 256;
        int row = idx >> 4;
        int q   = idx & 15;
        float4 v = reinterpret_cast<const float4*>(
            emb + ((size_t)(b0 + row) * NF + l) * EMB)[q];
        uint32_t* dst = sL + row * LPAD + q * 4;
        dst[0] = f2tf32(v.x); dst[1] = f2tf32(v.y);
        dst[2] = f2tf32(v.z); dst[3] = f2tf32(v.w);
    }

    // ---- stage W[p] transposed: sWt[e][d] = tf32(W[p][d][e]) ----
    // f4 index decomposed as d = f4 & 63 (lanes span banks), e4 = f4 >> 6
    {
        const float4* Wp = reinterpret_cast<const float4*>(W + (size_t)p * EMB * EMB);
        #pragma unroll
        for (int i = 0; i < 4; i++) {
            int f4 = tid + i * 256;           // 0..1023
            int d  = f4 & 63;
            int e4 = f4 >> 6;                 // 0..15
            float4 v = Wp[d * 16 + e4];
            sWt[(e4 * 4 + 0) * LPAD + d] = f2tf32(v.x);
            sWt[(e4 * 4 + 1) * LPAD + d] = f2tf32(v.y);
            sWt[(e4 * 4 + 2) * LPAD + d] = f2tf32(v.z);
            sWt[(e4 * 4 + 3) * LPAD + d] = f2tf32(v.w);
        }
    }
    __syncthreads();

    // ---- mma mainloop: warp computes rows [m0, m0+32) x all 64 cols ----
    const int warp = tid >> 5;
    const int lane = tid & 31;
    const int g    = lane >> 2;   // group id (0..7)
    const int t    = lane & 3;    // thread-in-group
    const int m0   = warp * 32;

    float c[2][8][4];
    #pragma unroll
    for (int mt = 0; mt < 2; mt++)
        #pragma unroll
        for (int nt = 0; nt < 8; nt++)
            #pragma unroll
            for (int j = 0; j < 4; j++) c[mt][nt][j] = 0.0f;

    #pragma unroll
    for (int kk = 0; kk < 8; kk++) {
        const int k0 = kk * 8;
        uint32_t a[2][4];
        #pragma unroll
        for (int mt = 0; mt < 2; mt++) {
            const uint32_t* base = sL + (m0 + mt * 16 + g) * LPAD + k0 + t;
            a[mt][0] = base[0];
            a[mt][1] = base[8 * LPAD];
            a[mt][2] = base[4];
            a[mt][3] = base[8 * LPAD + 4];
        }
        #pragma unroll
        for (int nt = 0; nt < 8; nt++) {
            const uint32_t* bb = sWt + (nt * 8 + g) * LPAD + k0 + t;
            uint32_t b0f = bb[0];
            uint32_t b1f = bb[4];
            mma_tf32(c[0][nt], a[0][0], a[0][1], a[0][2], a[0][3], b0f, b1f);
            mma_tf32(c[1][nt], a[1][0], a[1][1], a[1][2], a[1][3], b0f, b1f);
        }
    }

    // ---- epilogue: multiply by right-emb, store float2 (full 32B sectors) ----
    #pragma unroll
    for (int mt = 0; mt < 2; mt++) {
        #pragma unroll
        for (int nt = 0; nt < 8; nt++) {
            const int col0 = nt * 8 + 2 * t;
            const int row0 = b0 + m0 + mt * 16 + g;
            const int row1 = row0 + 8;

            float2 rv0 = __ldg(reinterpret_cast<const float2*>(
                emb + ((size_t)row0 * NF + r) * EMB + col0));
            float2 rv1 = __ldg(reinterpret_cast<const float2*>(
                emb + ((size_t)row1 * NF + r) * EMB + col0));

            float2 o0, o1;
            o0.x = c[mt][nt][0] * rv0.x;
            o0.y = c[mt][nt][1] * rv0.y;
            o1.x = c[mt][nt][2] * rv1.x;
            o1.y = c[mt][nt][3] * rv1.y;

            *reinterpret_cast<float2*>(
                out + ((size_t)row0 * PAIRS + p) * EMB + col0) = o0;
            *reinterpret_cast<float2*>(
                out + ((size_t)row1 * PAIRS + p) * EMB + col0) = o1;
        }
    }
}

extern "C" void kernel_launch(void* const* d_in, const int* in_sizes, int n_in,
                              void* d_out, int out_size)
{
    const float* emb  = (const float*)d_in[0];
    const float* W    = (const float*)d_in[1];
    const int*   lidx = (const int*)d_in[2];
    const int*   ridx = (const int*)d_in[3];
    float*       out  = (float*)d_out;

    cudaFuncSetAttribute(bilinear_mma_kernel,
                         cudaFuncAttributeMaxDynamicSharedMemorySize, SMEM_BYTES);

    dim3 grid(PAIRS, BATCH / TB);
    bilinear_mma_kernel<<<grid, 256, SMEM_BYTES>>>(emb, W, lidx, ridx, out);
}